// round 13
// baseline (speedup 1.0000x reference)
#include <cuda_runtime.h>

#define N_NODES 100000
#define N_EDGES 1600000
#define NFEAT   48
#define HIDDEN  256
#define TILE    128   // nodes per block in k_dot

// Scratch (no device allocation allowed -> __device__ globals)
__device__ float        g_w[NFEAT];     // fused W1@W2
__device__ float        g_c;            // fused bias term
__device__ unsigned int g_deg[N_NODES]; // edge-in count (self loop added in k_dot)
__device__ float        g_dinv[N_NODES];
__device__ float        g_z[N_NODES];   // z = (x.w) * dinv

// ---- node 2: degree count (u32), 4 edges/thread; block 0 also fuses weights ----
__global__ void k_count(const int* __restrict__ ei,
                        const float* __restrict__ W1,
                        const float* __restrict__ bias,
                        const float* __restrict__ W2,
                        const float* __restrict__ b2) {
    __shared__ float s_w2[HIDDEN];

    // Block 0: compute g_w = W1@W2 and g_c = bias*sum(W2)+b2 (L2-resident
    // weights; ~12K FMAs hidden inside this ~14us atomic-bound kernel).
    if (blockIdx.x == 0) {
        int t = threadIdx.x;          // blockDim == 256 == HIDDEN
        s_w2[t] = __ldg(&W2[t]);
    }
    __syncthreads();
    if (blockIdx.x == 0) {
        int t = threadIdx.x;
        if (t < NFEAT) {
            const float* r = W1 + t * HIDDEN;
            float acc = 0.f;
#pragma unroll 8
            for (int h = 0; h < HIDDEN; ++h) acc = fmaf(__ldg(&r[h]), s_w2[h], acc);
            g_w[t] = acc;
        }
        if (t == 0) {
            float s = 0.f;
            for (int h = 0; h < HIDDEN; ++h) s += s_w2[h];
            g_c = bias[0] * s + b2[0];
        }
    }

    int t = blockIdx.x * blockDim.x + threadIdx.x;
    if (t < N_EDGES / 4) {
        const int4* cols = reinterpret_cast<const int4*>(ei + N_EDGES);
        int4 c = __ldg(&cols[t]);
        atomicAdd(&g_deg[c.x], 1u);
        atomicAdd(&g_deg[c.y], 1u);
        atomicAdd(&g_deg[c.z], 1u);
        atomicAdd(&g_deg[c.w], 1u);
    }
}

// ---- node 3: y = x.w (coalesced smem tile); dinv; z; out = z*dinv + c ----
__global__ void __launch_bounds__(TILE) k_dot(const float* __restrict__ x,
                                              float* __restrict__ out) {
    __shared__ float sx[TILE * 49];   // stride-49 padding: conflict-free reads
    __shared__ float sw[NFEAT];

    int t    = threadIdx.x;
    int tile = blockIdx.x * TILE;
    int nn   = min(TILE, N_NODES - tile);

    if (t < NFEAT) sw[t] = g_w[t];

    const float4* src = reinterpret_cast<const float4*>(x + (size_t)tile * NFEAT);
    int nf4 = nn * (NFEAT / 4);
    for (int idx = t; idx < nf4; idx += TILE) {
        float4 v = __ldg(&src[idx]);
        int node = idx / 12;
        int f4   = idx - node * 12;
        float* d = &sx[node * 49 + f4 * 4];
        d[0] = v.x; d[1] = v.y; d[2] = v.z; d[3] = v.w;
    }
    __syncthreads();

    if (t < nn) {
        int i = tile + t;
        const float* r = &sx[t * 49];
        float a0 = 0.f, a1 = 0.f, a2 = 0.f, a3 = 0.f;
#pragma unroll
        for (int k = 0; k < NFEAT; k += 4) {
            a0 = fmaf(r[k + 0], sw[k + 0], a0);
            a1 = fmaf(r[k + 1], sw[k + 1], a1);
            a2 = fmaf(r[k + 2], sw[k + 2], a2);
            a3 = fmaf(r[k + 3], sw[k + 3], a3);
        }
        float y  = (a0 + a1) + (a2 + a3);
        float di = rsqrtf((float)(g_deg[i] + 1u));   // +1: self loop
        float z  = y * di;
        g_dinv[i] = di;
        g_z[i]    = z;
        out[i]    = fmaf(z, di, g_c);  // self-loop term + final norm + bias
    }
}

// ---- node 4: scatter + final fused: out[col] += z[row] * dinv[col] ----
__global__ void k_scatter(const int* __restrict__ ei, float* __restrict__ out) {
    int t = blockIdx.x * blockDim.x + threadIdx.x;
    if (t < N_EDGES / 4) {
        const int4* rows = reinterpret_cast<const int4*>(ei);
        const int4* cols = reinterpret_cast<const int4*>(ei + N_EDGES);
        int4 r = __ldg(&rows[t]);
        int4 c = __ldg(&cols[t]);
        float z0 = __ldg(&g_z[r.x]);
        float z1 = __ldg(&g_z[r.y]);
        float z2 = __ldg(&g_z[r.z]);
        float z3 = __ldg(&g_z[r.w]);
        float d0 = __ldg(&g_dinv[c.x]);
        float d1 = __ldg(&g_dinv[c.y]);
        float d2 = __ldg(&g_dinv[c.z]);
        float d3 = __ldg(&g_dinv[c.w]);
        atomicAdd(&out[c.x], z0 * d0);
        atomicAdd(&out[c.y], z1 * d1);
        atomicAdd(&out[c.z], z2 * d2);
        atomicAdd(&out[c.w], z3 * d3);
    }
}

extern "C" void kernel_launch(void* const* d_in, const int* in_sizes, int n_in,
                              void* d_out, int out_size) {
    const float* x    = (const float*)d_in[0];
    const int*   ei   = (const int*)  d_in[1];
    const float* W1   = (const float*)d_in[2];
    const float* bias = (const float*)d_in[3];
    const float* W2   = (const float*)d_in[4];
    const float* b2   = (const float*)d_in[5];
    float* out = (float*)d_out;

    const int TB = 256;
    const int nb_e4   = (N_EDGES / 4 + TB - 1) / TB;   // 1563
    const int nb_node = (N_NODES + TILE - 1) / TILE;   // 782

    // node 1: degree init via memset (cheap graph node)
    void* deg_ptr = nullptr;
    cudaGetSymbolAddress(&deg_ptr, g_deg);
    cudaMemsetAsync(deg_ptr, 0, N_NODES * sizeof(unsigned int), 0);

    // linear chain - minimal node count, no streams/events
    k_count  <<<nb_e4,   TB>>>(ei, W1, bias, W2, b2);
    k_dot    <<<nb_node, TILE>>>(x, out);
    k_scatter<<<nb_e4,   TB>>>(ei, out);
}

// round 15
// speedup vs baseline: 1.3052x; 1.3052x over previous
#include <cuda_runtime.h>

#define N_NODES 100000
#define N_EDGES 1600000
#define NFEAT   48
#define HIDDEN  256
#define TILE    128   // nodes per block in k_dot

// Scratch (no device allocation allowed -> __device__ globals)
__device__ float        g_w[NFEAT];     // fused W1@W2
__device__ float        g_c;            // fused bias term
__device__ unsigned int g_deg[N_NODES]; // edge-in count (self loop added in k_dot)
__device__ float        g_dinv[N_NODES];
__device__ float        g_z[N_NODES];   // z = (x.w) * dinv

// ---- node 2: degree count (u32), 4 edges/thread; block 0 also fuses weights ----
__global__ void k_count(const int* __restrict__ ei,
                        const float* __restrict__ W1,
                        const float* __restrict__ bias,
                        const float* __restrict__ W2,
                        const float* __restrict__ b2) {
    // Block 0: g_w = W1@W2, g_c = bias*sum(W2)+b2 -- warp-parallel, float4
    // loads, shuffle reduce. All loads independent => ~1 memory round trip,
    // genuinely hidden inside this ~14us atomic-bound kernel (R13 lesson:
    // the 48-thread serial version became a 12us kernel tail).
    if (blockIdx.x == 0) {
        int lane = threadIdx.x & 31;
        int warp = threadIdx.x >> 5;          // 8 warps
        const float4* w2v = reinterpret_cast<const float4*>(W2);   // 64 float4

        // 8 warps x 6 features
        for (int f = warp; f < NFEAT; f += 8) {
            const float4* r = reinterpret_cast<const float4*>(W1 + f * HIDDEN);
            float acc = 0.f;
#pragma unroll
            for (int j = 0; j < 2; ++j) {     // lanes cover 64 float4
                float4 a = __ldg(&r[lane + 32 * j]);
                float4 b = __ldg(&w2v[lane + 32 * j]);
                acc += a.x * b.x + a.y * b.y + a.z * b.z + a.w * b.w;
            }
#pragma unroll
            for (int o = 16; o > 0; o >>= 1)
                acc += __shfl_down_sync(0xffffffffu, acc, o);
            if (lane == 0) g_w[f] = acc;
        }
        // warp 0: g_c
        if (warp == 0) {
            float s = 0.f;
#pragma unroll
            for (int j = 0; j < 2; ++j) {
                float4 b = __ldg(&w2v[lane + 32 * j]);
                s += b.x + b.y + b.z + b.w;
            }
#pragma unroll
            for (int o = 16; o > 0; o >>= 1)
                s += __shfl_down_sync(0xffffffffu, s, o);
            if (lane == 0) g_c = bias[0] * s + b2[0];
        }
    }

    int t = blockIdx.x * blockDim.x + threadIdx.x;
    if (t < N_EDGES / 4) {
        const int4* cols = reinterpret_cast<const int4*>(ei + N_EDGES);
        int4 c = __ldg(&cols[t]);
        atomicAdd(&g_deg[c.x], 1u);
        atomicAdd(&g_deg[c.y], 1u);
        atomicAdd(&g_deg[c.z], 1u);
        atomicAdd(&g_deg[c.w], 1u);
    }
}

// ---- node 3: y = x.w (coalesced smem tile); dinv; z; out = z*dinv + c ----
__global__ void __launch_bounds__(TILE) k_dot(const float* __restrict__ x,
                                              float* __restrict__ out) {
    __shared__ float sx[TILE * 49];   // stride-49 padding: conflict-free reads
    __shared__ float sw[NFEAT];

    int t    = threadIdx.x;
    int tile = blockIdx.x * TILE;
    int nn   = min(TILE, N_NODES - tile);

    if (t < NFEAT) sw[t] = g_w[t];

    const float4* src = reinterpret_cast<const float4*>(x + (size_t)tile * NFEAT);
    int nf4 = nn * (NFEAT / 4);
    for (int idx = t; idx < nf4; idx += TILE) {
        float4 v = __ldg(&src[idx]);
        int node = idx / 12;
        int f4   = idx - node * 12;
        float* d = &sx[node * 49 + f4 * 4];
        d[0] = v.x; d[1] = v.y; d[2] = v.z; d[3] = v.w;
    }
    __syncthreads();

    if (t < nn) {
        int i = tile + t;
        const float* r = &sx[t * 49];
        float a0 = 0.f, a1 = 0.f, a2 = 0.f, a3 = 0.f;
#pragma unroll
        for (int k = 0; k < NFEAT; k += 4) {
            a0 = fmaf(r[k + 0], sw[k + 0], a0);
            a1 = fmaf(r[k + 1], sw[k + 1], a1);
            a2 = fmaf(r[k + 2], sw[k + 2], a2);
            a3 = fmaf(r[k + 3], sw[k + 3], a3);
        }
        float y  = (a0 + a1) + (a2 + a3);
        float di = rsqrtf((float)(g_deg[i] + 1u));   // +1: self loop
        float z  = y * di;
        g_dinv[i] = di;
        g_z[i]    = z;
        out[i]    = fmaf(z, di, g_c);  // self-loop term + final norm + bias
    }
}

// ---- node 4: scatter + final fused: out[col] += z[row] * dinv[col] ----
__global__ void k_scatter(const int* __restrict__ ei, float* __restrict__ out) {
    int t = blockIdx.x * blockDim.x + threadIdx.x;
    if (t < N_EDGES / 4) {
        const int4* rows = reinterpret_cast<const int4*>(ei);
        const int4* cols = reinterpret_cast<const int4*>(ei + N_EDGES);
        int4 r = __ldg(&rows[t]);
        int4 c = __ldg(&cols[t]);
        float z0 = __ldg(&g_z[r.x]);
        float z1 = __ldg(&g_z[r.y]);
        float z2 = __ldg(&g_z[r.z]);
        float z3 = __ldg(&g_z[r.w]);
        float d0 = __ldg(&g_dinv[c.x]);
        float d1 = __ldg(&g_dinv[c.y]);
        float d2 = __ldg(&g_dinv[c.z]);
        float d3 = __ldg(&g_dinv[c.w]);
        atomicAdd(&out[c.x], z0 * d0);
        atomicAdd(&out[c.y], z1 * d1);
        atomicAdd(&out[c.z], z2 * d2);
        atomicAdd(&out[c.w], z3 * d3);
    }
}

extern "C" void kernel_launch(void* const* d_in, const int* in_sizes, int n_in,
                              void* d_out, int out_size) {
    const float* x    = (const float*)d_in[0];
    const int*   ei   = (const int*)  d_in[1];
    const float* W1   = (const float*)d_in[2];
    const float* bias = (const float*)d_in[3];
    const float* W2   = (const float*)d_in[4];
    const float* b2   = (const float*)d_in[5];
    float* out = (float*)d_out;

    const int TB = 256;
    const int nb_e4   = (N_EDGES / 4 + TB - 1) / TB;   // 1563
    const int nb_node = (N_NODES + TILE - 1) / TILE;   // 782

    // node 1: degree init via memset (cheap graph node)
    void* deg_ptr = nullptr;
    cudaGetSymbolAddress(&deg_ptr, g_deg);
    cudaMemsetAsync(deg_ptr, 0, N_NODES * sizeof(unsigned int), 0);

    // linear chain - minimal node count, no streams/events
    k_count  <<<nb_e4,   TB>>>(ei, W1, bias, W2, b2);
    k_dot    <<<nb_node, TILE>>>(x, out);
    k_scatter<<<nb_e4,   TB>>>(ei, out);
}